// round 6
// baseline (speedup 1.0000x reference)
#include <cuda_runtime.h>
#include <math.h>
#include <stdint.h>

#define Bdim 8
#define Ndim 256
#define Ddim 128
#define K2   256

// Scratch for per-node projections (allocation-free rule -> device globals)
__device__ float g_Pi[Bdim * Ndim * K2];
__device__ float g_Pj[Bdim * Ndim * K2];

// ---------------------------------------------------------------------------
// Kernel 1 (proven): Pi = x@W1a + x_next@W1b + b1 ; Pj = x@W1c + x_next@W1d
// ---------------------------------------------------------------------------
__global__ void __launch_bounds__(256) proj_kernel(
    const float* __restrict__ x, const float* __restrict__ W1,
    const float* __restrict__ b1, float* __restrict__ outTour, int hasTour)
{
    __shared__ float xr[9][128];
    const int b  = blockIdx.x;
    const int n0 = blockIdx.y * 8;
    const int tid = threadIdx.x;

    for (int idx = tid; idx < 9 * 128; idx += 256) {
        int r = idx >> 7, c = idx & 127;
        int n = (n0 + r) & (Ndim - 1);
        xr[r][c] = x[((b * Ndim) + n) * Ddim + c];
    }
    __syncthreads();

    const int c = tid;
    float accPi[8], accPj[8];
#pragma unroll
    for (int r = 0; r < 8; r++) { accPi[r] = 0.f; accPj[r] = 0.f; }

    for (int k = 0; k < 128; k++) {
        float wa = W1[(k      ) * 256 + c];
        float wb = W1[(k + 128) * 256 + c];
        float wc = W1[(k + 256) * 256 + c];
        float wd = W1[(k + 384) * 256 + c];
#pragma unroll
        for (int r = 0; r < 8; r++) {
            float xi = xr[r][k];
            float xn = xr[r + 1][k];
            accPi[r] = fmaf(xi, wa, accPi[r]);
            accPi[r] = fmaf(xn, wb, accPi[r]);
            accPj[r] = fmaf(xi, wc, accPj[r]);
            accPj[r] = fmaf(xn, wd, accPj[r]);
        }
    }
    const float bias = b1[c];
#pragma unroll
    for (int r = 0; r < 8; r++) {
        int n = n0 + r;
        g_Pi[((b * Ndim) + n) * K2 + c] = accPi[r] + bias;
        g_Pj[((b * Ndim) + n) * K2 + c] = accPj[r];
    }
    if (hasTour && tid < 8) outTour[b * Ndim + n0 + tid] = (float)(n0 + tid);
}

// ---------------------------------------------------------------------------
// mma.sync m16n8k8 tf32 (verified layout R3/R5)
// ---------------------------------------------------------------------------
__device__ __forceinline__ void mma_tf32(float* d, const uint32_t* a,
                                         const uint32_t* b) {
    asm volatile(
        "mma.sync.aligned.m16n8k8.row.col.f32.tf32.tf32.f32 "
        "{%0,%1,%2,%3},{%4,%5,%6,%7},{%8,%9},{%0,%1,%2,%3};\n"
        : "+f"(d[0]), "+f"(d[1]), "+f"(d[2]), "+f"(d[3])
        : "r"(a[0]), "r"(a[1]), "r"(a[2]), "r"(a[3]), "r"(b[0]), "r"(b[1]));
}

__device__ __forceinline__ void cpa16(uint32_t dst, const void* src) {
    asm volatile("cp.async.ca.shared.global [%0], [%1], 16;"
                 :: "r"(dst), "l"(src) : "memory");
}
__device__ __forceinline__ uint32_t smem_u32(const void* p) {
    uint32_t a;
    asm("{ .reg .u64 t; cvta.to.shared.u64 t, %1; cvt.u32.u64 %0, t; }"
        : "=r"(a) : "l"(p));
    return a;
}

// ---------------------------------------------------------------------------
// SMEM layout (floats)
// ---------------------------------------------------------------------------
#define PIS 260
#define OFF_W2F 0                         // packed B fragments: 32768 floats
#define OFF_PI0 32768                     // 32*260 = 8320
#define OFF_PI1 (OFF_PI0 + 32 * PIS)      // 41088
#define OFF_PJ0 (OFF_PI1 + 32 * PIS)      // 49408 ; 8*260 = 2080
#define OFF_PJ1 (OFF_PJ0 + 8 * PIS)       // 51488
#define OFF_B2  (OFF_PJ1 + 8 * PIS)       // 53568
#define OFF_W3  (OFF_B2 + 128)            // 53696
#define OFF_RED (OFF_W3 + 128)            // 53824 ; 512 floats
#define SMEM_FLOATS (OFF_RED + 512)       // 54336 -> 217344 bytes
#define SMEM_BYTES (SMEM_FLOATS * 4)

#define NTILES_PER_B 144                  // sum_{bi=0..7} (32 - 4*bi)
#define NTILES_TOT   (Bdim * NTILES_PER_B)    // 1152
#define GRID_PAIR    152
#define NTHREADS     512

__device__ __forceinline__ void tile_coords(int t, int& b, int& i0, int& j0) {
    b = t / NTILES_PER_B;
    int r = t - b * NTILES_PER_B;
    int bi = 0;
    while (r >= 32 - 4 * bi) { r -= 32 - 4 * bi; bi++; }
    i0 = bi * 32;
    j0 = (4 * bi + r) * 8;
}

// ---------------------------------------------------------------------------
// Kernel 2: persistent mma.sync tf32 pair kernel.
// CTA tile: M=256 pairs (32 i x 8 j), N=128 outs, K=256. 16 warps (8M x 2N).
// Conflict-free packed B fragments (R5); cp.async double-buffered Pi/Pj
// tile staging; register-rotated (software-pipelined) k-loop.
// ---------------------------------------------------------------------------
__global__ void __launch_bounds__(NTHREADS, 1) pair_mma_kernel(
    const float* __restrict__ W2g, const float* __restrict__ b2g,
    const float* __restrict__ W3g, const float* __restrict__ b3g,
    float* __restrict__ outM)
{
    extern __shared__ float sm[];
    float4* sW2f4 = (float4*)(sm + OFF_W2F);
    float* sB2  = sm + OFF_B2;
    float* sW3  = sm + OFF_W3;
    float* sRed = sm + OFF_RED;
    const uint32_t sbase = smem_u32(sm);

    const int tid  = threadIdx.x;
    const int wid  = tid >> 5;
    const int lane = tid & 31;
    const int q = lane >> 2;     // fragment group id
    const int c = lane & 3;      // thread-in-group

    // --- pack B fragments (one-time): float4 idx ((s*4+g)*2+wn)*32+lane ---
    for (int idx = tid; idx < 8192; idx += NTHREADS) {
        int ln  = idx & 31;
        int wnn = (idx >> 5) & 1;
        int g   = (idx >> 6) & 3;
        int s   = idx >> 8;
        int cc  = ln & 3, qq = ln >> 2;
        int k1  = 8 * s + cc, k2 = k1 + 4;
        int n0  = 64 * wnn + 16 * g + qq;
        int n1  = n0 + 8;
        float4 v;
        v.x = W2g[k1 * 128 + n0];
        v.y = W2g[k2 * 128 + n0];
        v.z = W2g[k1 * 128 + n1];
        v.w = W2g[k2 * 128 + n1];
        sW2f4[idx] = v;
    }
    if (tid < 128) { sB2[tid] = b2g[tid]; sW3[tid] = W3g[tid]; }
    const float b3v = b3g[0];

    const int wm = wid >> 1;
    const int wn = wid & 1;
    const int mb = wm * 32;
    const int nb = wn * 64;
    const float4* myB = sW2f4 + wn * 32 + lane;   // + (s*4+g)*64

    // --- prefetch first tile's Pi/Pj into buffer 0 ---
    {
        int b, i0, j0;
        tile_coords(blockIdx.x, b, i0, j0);
        const float* gPi = g_Pi + (size_t)(b * Ndim + i0) * K2;
        const float* gPj = g_Pj + (size_t)(b * Ndim + j0) * K2;
#pragma unroll
        for (int u = 0; u < 4; u++) {
            int idx = u * NTHREADS + tid;            // 0..2047
            int row = idx >> 6, k4 = (idx & 63) << 2;
            cpa16(sbase + (OFF_PI0 + row * PIS + k4) * 4, gPi + row * 256 + k4);
        }
        {
            int row = tid >> 6, k4 = (tid & 63) << 2;
            cpa16(sbase + (OFF_PJ0 + row * PIS + k4) * 4, gPj + row * 256 + k4);
        }
        asm volatile("cp.async.commit_group;" ::: "memory");
    }

    int cnt = 0;
    for (int t = blockIdx.x; t < NTILES_TOT; t += GRID_PAIR, cnt++) {
        const int buf = cnt & 1;
        const bool havenext = (t + GRID_PAIR < NTILES_TOT);

        // prefetch next tile into the other buffer
        if (havenext) {
            int b, i0, j0;
            tile_coords(t + GRID_PAIR, b, i0, j0);
            const float* gPi = g_Pi + (size_t)(b * Ndim + i0) * K2;
            const float* gPj = g_Pj + (size_t)(b * Ndim + j0) * K2;
            const int piO = buf ? OFF_PI0 : OFF_PI1;
            const int pjO = buf ? OFF_PJ0 : OFF_PJ1;
#pragma unroll
            for (int u = 0; u < 4; u++) {
                int idx = u * NTHREADS + tid;
                int row = idx >> 6, k4 = (idx & 63) << 2;
                cpa16(sbase + (piO + row * PIS + k4) * 4, gPi + row * 256 + k4);
            }
            {
                int row = tid >> 6, k4 = (tid & 63) << 2;
                cpa16(sbase + (pjO + row * PIS + k4) * 4, gPj + row * 256 + k4);
            }
            asm volatile("cp.async.commit_group;" ::: "memory");
            asm volatile("cp.async.wait_group 1;" ::: "memory");
        } else {
            asm volatile("cp.async.wait_group 0;" ::: "memory");
        }
        __syncthreads();   // current tile's Pi/Pj visible to all threads

        int b, i0, j0;
        tile_coords(t, b, i0, j0);

        const float* sPi = sm + (buf ? OFF_PI1 : OFF_PI0);
        const float* sPj = sm + (buf ? OFF_PJ1 : OFF_PJ0);
        const float* piR0 = sPi + ((mb >> 3) + 0) * PIS + q;  // +k offset applied
        const float* piR1 = sPi + ((mb >> 3) + 1) * PIS + q - q; // keep simple
        // (use direct indexing below instead of fancy pointer tricks)
        const float* pR0 = sPi + ((mb >> 3) + 0) * PIS;
        const float* pR1 = sPi + ((mb >> 3) + 1) * PIS;
        const float* pR2 = sPi + ((mb >> 3) + 2) * PIS;
        const float* pR3 = sPi + ((mb >> 3) + 3) * PIS;
        const float* pjR = sPj + q * PIS;
        (void)piR0; (void)piR1;

        float acc[2][8][4];
#pragma unroll
        for (int am = 0; am < 2; am++)
#pragma unroll
            for (int a = 0; a < 8; a++)
#pragma unroll
                for (int e = 0; e < 4; e++) acc[am][a][e] = 0.f;

        // ---- software-pipelined k-loop ----
        float pr[8], pj0, pj1;
        float4 bq[4];
        {
            const int k1 = c, k2 = c + 4;
            pr[0] = pR0[k1]; pr[1] = pR1[k1]; pr[2] = pR2[k1]; pr[3] = pR3[k1];
            pr[4] = pR0[k2]; pr[5] = pR1[k2]; pr[6] = pR2[k2]; pr[7] = pR3[k2];
            pj0 = pjR[k1]; pj1 = pjR[k2];
            bq[0] = myB[0 * 64]; bq[1] = myB[1 * 64];
            bq[2] = myB[2 * 64]; bq[3] = myB[3 * 64];
        }
#pragma unroll 2
        for (int s = 0; s < 32; s++) {
            float prn[8], pjn0 = 0.f, pjn1 = 0.f;
            float4 bqn[4];
            if (s < 31) {
                const int k1 = 8 * (s + 1) + c, k2 = k1 + 4;
                prn[0] = pR0[k1]; prn[1] = pR1[k1];
                prn[2] = pR2[k1]; prn[3] = pR3[k1];
                prn[4] = pR0[k2]; prn[5] = pR1[k2];
                prn[6] = pR2[k2]; prn[7] = pR3[k2];
                pjn0 = pjR[k1]; pjn1 = pjR[k2];
                bqn[0] = myB[((s + 1) * 4 + 0) * 64];
                bqn[1] = myB[((s + 1) * 4 + 1) * 64];
                bqn[2] = myB[((s + 1) * 4 + 2) * 64];
                bqn[3] = myB[((s + 1) * 4 + 3) * 64];
            } else {
#pragma unroll
                for (int u = 0; u < 8; u++) prn[u] = 0.f;
                bqn[0] = bqn[1] = bqn[2] = bqn[3] = make_float4(0.f, 0.f, 0.f, 0.f);
            }

            uint32_t bf[8][2];
            bf[0][0] = __float_as_uint(bq[0].x); bf[0][1] = __float_as_uint(bq[0].y);
            bf[1][0] = __float_as_uint(bq[0].z); bf[1][1] = __float_as_uint(bq[0].w);
            bf[2][0] = __float_as_uint(bq[1].x); bf[2][1] = __float_as_uint(bq[1].y);
            bf[3][0] = __float_as_uint(bq[1].z); bf[3][1] = __float_as_uint(bq[1].w);
            bf[4][0] = __float_as_uint(bq[2].x); bf[4][1] = __float_as_uint(bq[2].y);
            bf[5][0] = __float_as_uint(bq[2].z); bf[5][1] = __float_as_uint(bq[2].w);
            bf[6][0] = __float_as_uint(bq[3].x); bf[6][1] = __float_as_uint(bq[3].y);
            bf[7][0] = __float_as_uint(bq[3].z); bf[7][1] = __float_as_uint(bq[3].w);

            {   // M-atom 0: rows mb+q, mb+q+8
                uint32_t af[4];
                af[0] = __float_as_uint(fmaxf(pr[0] + pj0, 0.f));
                af[1] = __float_as_uint(fmaxf(pr[1] + pj0, 0.f));
                af[2] = __float_as_uint(fmaxf(pr[4] + pj1, 0.f));
                af[3] = __float_as_uint(fmaxf(pr[5] + pj1, 0.f));
#pragma unroll
                for (int a = 0; a < 8; a++) mma_tf32(acc[0][a], af, bf[a]);
            }
            {   // M-atom 1: rows mb+q+16, mb+q+24
                uint32_t af[4];
                af[0] = __float_as_uint(fmaxf(pr[2] + pj0, 0.f));
                af[1] = __float_as_uint(fmaxf(pr[3] + pj0, 0.f));
                af[2] = __float_as_uint(fmaxf(pr[6] + pj1, 0.f));
                af[3] = __float_as_uint(fmaxf(pr[7] + pj1, 0.f));
#pragma unroll
                for (int a = 0; a < 8; a++) mma_tf32(acc[1][a], af, bf[a]);
            }

#pragma unroll
            for (int u = 0; u < 8; u++) pr[u] = prn[u];
            pj0 = pjn0; pj1 = pjn1;
            bq[0] = bqn[0]; bq[1] = bqn[1]; bq[2] = bqn[2]; bq[3] = bqn[3];
        }

        // ---- epilogue ----
#pragma unroll
        for (int am = 0; am < 2; am++) {
            float s0 = 0.f, s1 = 0.f;
#pragma unroll
            for (int a = 0; a < 8; a++) {
                int n0 = nb + 8 * a + 2 * c;
                float w0 = sW3[n0], w1 = sW3[n0 + 1];
                float bb0 = sB2[n0], bb1 = sB2[n0 + 1];
                s0 = fmaf(fmaxf(acc[am][a][0] + bb0, 0.f), w0, s0);
                s0 = fmaf(fmaxf(acc[am][a][1] + bb1, 0.f), w1, s0);
                s1 = fmaf(fmaxf(acc[am][a][2] + bb0, 0.f), w0, s1);
                s1 = fmaf(fmaxf(acc[am][a][3] + bb1, 0.f), w1, s1);
            }
            s0 += __shfl_xor_sync(0xffffffffu, s0, 1);
            s0 += __shfl_xor_sync(0xffffffffu, s0, 2);
            s1 += __shfl_xor_sync(0xffffffffu, s1, 1);
            s1 += __shfl_xor_sync(0xffffffffu, s1, 2);
            if (c == 0) {
                int m0 = mb + am * 16 + q;
                sRed[m0 * 2 + wn]       = s0;
                sRed[(m0 + 8) * 2 + wn] = s1;
            }
        }
        __syncthreads();

        if (tid < 256) {
            float s = sRed[tid * 2] + sRed[tid * 2 + 1];
            float val = tanhf(s + b3v);
            int i = i0 + (tid >> 3), j = j0 + (tid & 7);
            bool valid = (j >= i + 2) && ((j - i) != (Ndim - 1));
            outM[(b * Ndim + i) * Ndim + j] = valid ? val : 0.f;
        }
        __syncthreads();  // sRed + Pi/Pj buffer reuse guard
    }
}

// ---------------------------------------------------------------------------
extern "C" void kernel_launch(void* const* d_in, const int* in_sizes, int n_in,
                              void* d_out, int out_size) {
    const float* x  = (const float*)d_in[0];
    const float* W1 = (const float*)d_in[1];
    const float* b1 = (const float*)d_in[2];
    const float* W2 = (const float*)d_in[3];
    const float* b2 = (const float*)d_in[4];
    const float* W3 = (const float*)d_in[5];
    const float* b3 = (const float*)d_in[6];

    float* out = (float*)d_out;
    const int matElems  = Bdim * Ndim * Ndim;
    const int tourElems = Bdim * Ndim;
    int hasTour = (out_size >= matElems + tourElems) ? 1 : 0;
    float* outTour = out;
    float* outM    = hasTour ? (out + tourElems) : out;

    // zero matrix region (covers fully-masked tiles); computed tiles overwrite
    cudaMemsetAsync(outM, 0, (size_t)matElems * sizeof(float), 0);

    dim3 g1(Bdim, Ndim / 8);
    proj_kernel<<<g1, 256>>>(x, W1, b1, outTour, hasTour);

    cudaFuncSetAttribute(pair_mma_kernel, cudaFuncAttributeMaxDynamicSharedMemorySize,
                         SMEM_BYTES);
    pair_mma_kernel<<<GRID_PAIR, NTHREADS, SMEM_BYTES>>>(W2, b2, W3, b3, outM);
}

// round 7
// speedup vs baseline: 1.5725x; 1.5725x over previous
#include <cuda_runtime.h>
#include <math.h>
#include <stdint.h>

#define Bdim 8
#define Ndim 256
#define Ddim 128
#define K2   256

// Scratch for per-node projections (allocation-free rule -> device globals)
__device__ float g_Pi[Bdim * Ndim * K2];
__device__ float g_Pj[Bdim * Ndim * K2];

// ---------------------------------------------------------------------------
// Kernel 1 (proven): Pi = x@W1a + x_next@W1b + b1 ; Pj = x@W1c + x_next@W1d
// ---------------------------------------------------------------------------
__global__ void __launch_bounds__(256) proj_kernel(
    const float* __restrict__ x, const float* __restrict__ W1,
    const float* __restrict__ b1, float* __restrict__ outTour, int hasTour)
{
    __shared__ float xr[9][128];
    const int b  = blockIdx.x;
    const int n0 = blockIdx.y * 8;
    const int tid = threadIdx.x;

    for (int idx = tid; idx < 9 * 128; idx += 256) {
        int r = idx >> 7, c = idx & 127;
        int n = (n0 + r) & (Ndim - 1);
        xr[r][c] = x[((b * Ndim) + n) * Ddim + c];
    }
    __syncthreads();

    const int c = tid;
    float accPi[8], accPj[8];
#pragma unroll
    for (int r = 0; r < 8; r++) { accPi[r] = 0.f; accPj[r] = 0.f; }

    for (int k = 0; k < 128; k++) {
        float wa = W1[(k      ) * 256 + c];
        float wb = W1[(k + 128) * 256 + c];
        float wc = W1[(k + 256) * 256 + c];
        float wd = W1[(k + 384) * 256 + c];
#pragma unroll
        for (int r = 0; r < 8; r++) {
            float xi = xr[r][k];
            float xn = xr[r + 1][k];
            accPi[r] = fmaf(xi, wa, accPi[r]);
            accPi[r] = fmaf(xn, wb, accPi[r]);
            accPj[r] = fmaf(xi, wc, accPj[r]);
            accPj[r] = fmaf(xn, wd, accPj[r]);
        }
    }
    const float bias = b1[c];
#pragma unroll
    for (int r = 0; r < 8; r++) {
        int n = n0 + r;
        g_Pi[((b * Ndim) + n) * K2 + c] = accPi[r] + bias;
        g_Pj[((b * Ndim) + n) * K2 + c] = accPj[r];
    }
    if (hasTour && tid < 8) outTour[b * Ndim + n0 + tid] = (float)(n0 + tid);
}

// ---------------------------------------------------------------------------
// mma.sync m16n8k8 tf32 (verified layout R3/R5)
// ---------------------------------------------------------------------------
__device__ __forceinline__ void mma_tf32(float* d, const uint32_t* a,
                                         const uint32_t* b) {
    asm volatile(
        "mma.sync.aligned.m16n8k8.row.col.f32.tf32.tf32.f32 "
        "{%0,%1,%2,%3},{%4,%5,%6,%7},{%8,%9},{%0,%1,%2,%3};\n"
        : "+f"(d[0]), "+f"(d[1]), "+f"(d[2]), "+f"(d[3])
        : "r"(a[0]), "r"(a[1]), "r"(a[2]), "r"(a[3]), "r"(b[0]), "r"(b[1]));
}

__device__ __forceinline__ void cpa16(uint32_t dst, const void* src) {
    asm volatile("cp.async.ca.shared.global [%0], [%1], 16;"
                 :: "r"(dst), "l"(src) : "memory");
}
__device__ __forceinline__ uint32_t smem_u32(const void* p) {
    uint32_t a;
    asm("{ .reg .u64 t; cvta.to.shared.u64 t, %1; cvt.u32.u64 %0, t; }"
        : "=r"(a) : "l"(p));
    return a;
}

// ---------------------------------------------------------------------------
// SMEM layout (floats)
// ---------------------------------------------------------------------------
#define PIS 260
#define OFF_W2F 0                         // packed B fragments: 32768 floats
#define OFF_PI0 32768                     // 32*260 = 8320
#define OFF_PI1 (OFF_PI0 + 32 * PIS)      // 41088
#define OFF_PJ0 (OFF_PI1 + 32 * PIS)      // 49408 ; 8*260 = 2080
#define OFF_PJ1 (OFF_PJ0 + 8 * PIS)       // 51488
#define OFF_B2  (OFF_PJ1 + 8 * PIS)       // 53568
#define OFF_W3  (OFF_B2 + 128)            // 53696
#define OFF_RED (OFF_W3 + 128)            // 53824 ; 512 floats
#define SMEM_FLOATS (OFF_RED + 512)       // 54336 -> 217344 bytes
#define SMEM_BYTES (SMEM_FLOATS * 4)

#define NTILES_PER_B 144                  // sum_{bi=0..7} (32 - 4*bi)
#define NTILES_TOT   (Bdim * NTILES_PER_B)    // 1152
#define GRID_PAIR    152
#define NTHREADS     512

__device__ __forceinline__ void tile_coords(int t, int& b, int& i0, int& j0) {
    b = t / NTILES_PER_B;
    int r = t - b * NTILES_PER_B;
    int bi = 0;
    while (r >= 32 - 4 * bi) { r -= 32 - 4 * bi; bi++; }
    i0 = bi * 32;
    j0 = (4 * bi + r) * 8;
}

// ---------------------------------------------------------------------------
// Kernel 2: persistent mma.sync tf32 pair kernel.
// CTA tile: M=256 pairs (32 i x 8 j), N=128 outs, K=256. 16 warps (8M x 2N).
// R5's k-loop (compiler-scheduled, unroll 4) + cp.async double-buffered
// Pi/Pj tile staging. Conflict-free packed B fragments.
// ---------------------------------------------------------------------------
__global__ void __launch_bounds__(NTHREADS, 1) pair_mma_kernel(
    const float* __restrict__ W2g, const float* __restrict__ b2g,
    const float* __restrict__ W3g, const float* __restrict__ b3g,
    float* __restrict__ outM)
{
    extern __shared__ float sm[];
    float4* sW2f4 = (float4*)(sm + OFF_W2F);
    float* sB2  = sm + OFF_B2;
    float* sW3  = sm + OFF_W3;
    float* sRed = sm + OFF_RED;
    const uint32_t sbase = smem_u32(sm);

    const int tid  = threadIdx.x;
    const int wid  = tid >> 5;
    const int lane = tid & 31;
    const int q = lane >> 2;     // fragment group id
    const int c = lane & 3;      // thread-in-group

    // --- pack B fragments (one-time): float4 idx ((s*4+g)*2+wn)*32+lane ---
    for (int idx = tid; idx < 8192; idx += NTHREADS) {
        int ln  = idx & 31;
        int wnn = (idx >> 5) & 1;
        int g   = (idx >> 6) & 3;
        int s   = idx >> 8;
        int cc  = ln & 3, qq = ln >> 2;
        int k1  = 8 * s + cc, k2 = k1 + 4;
        int n0  = 64 * wnn + 16 * g + qq;
        int n1  = n0 + 8;
        float4 v;
        v.x = W2g[k1 * 128 + n0];
        v.y = W2g[k2 * 128 + n0];
        v.z = W2g[k1 * 128 + n1];
        v.w = W2g[k2 * 128 + n1];
        sW2f4[idx] = v;
    }
    if (tid < 128) { sB2[tid] = b2g[tid]; sW3[tid] = W3g[tid]; }
    const float b3v = b3g[0];

    const int wm = wid >> 1;
    const int wn = wid & 1;
    const int mb = wm * 32;
    const int nb = wn * 64;
    const float4* myB = sW2f4 + wn * 32 + lane;   // + (s*4+g)*64

    // --- prefetch first tile's Pi/Pj into buffer 0 ---
    {
        int b, i0, j0;
        tile_coords(blockIdx.x, b, i0, j0);
        const float* gPi = g_Pi + (size_t)(b * Ndim + i0) * K2;
        const float* gPj = g_Pj + (size_t)(b * Ndim + j0) * K2;
#pragma unroll
        for (int u = 0; u < 4; u++) {
            int idx = u * NTHREADS + tid;            // 0..2047
            int row = idx >> 6, k4 = (idx & 63) << 2;
            cpa16(sbase + (OFF_PI0 + row * PIS + k4) * 4, gPi + row * 256 + k4);
        }
        {
            int row = tid >> 6, k4 = (tid & 63) << 2;
            cpa16(sbase + (OFF_PJ0 + row * PIS + k4) * 4, gPj + row * 256 + k4);
        }
        asm volatile("cp.async.commit_group;" ::: "memory");
    }

    int cnt = 0;
    for (int t = blockIdx.x; t < NTILES_TOT; t += GRID_PAIR, cnt++) {
        const int buf = cnt & 1;

        // prefetch next tile into the other buffer, then wait for current
        if (t + GRID_PAIR < NTILES_TOT) {
            int b, i0, j0;
            tile_coords(t + GRID_PAIR, b, i0, j0);
            const float* gPi = g_Pi + (size_t)(b * Ndim + i0) * K2;
            const float* gPj = g_Pj + (size_t)(b * Ndim + j0) * K2;
            const int piO = buf ? OFF_PI0 : OFF_PI1;
            const int pjO = buf ? OFF_PJ0 : OFF_PJ1;
#pragma unroll
            for (int u = 0; u < 4; u++) {
                int idx = u * NTHREADS + tid;
                int row = idx >> 6, k4 = (idx & 63) << 2;
                cpa16(sbase + (piO + row * PIS + k4) * 4, gPi + row * 256 + k4);
            }
            {
                int row = tid >> 6, k4 = (tid & 63) << 2;
                cpa16(sbase + (pjO + row * PIS + k4) * 4, gPj + row * 256 + k4);
            }
            asm volatile("cp.async.commit_group;" ::: "memory");
            asm volatile("cp.async.wait_group 1;" ::: "memory");
        } else {
            asm volatile("cp.async.wait_group 0;" ::: "memory");
        }
        __syncthreads();   // current tile's Pi/Pj visible; also guards sRed reuse

        int b, i0, j0;
        tile_coords(t, b, i0, j0);

        const float* sPi = sm + (buf ? OFF_PI1 : OFF_PI0);
        const float* sPj = sm + (buf ? OFF_PJ1 : OFF_PJ0);
        const float* piR0 = sPi + ((mb >> 3) + 0) * PIS;  // rows mb+q
        const float* piR1 = sPi + ((mb >> 3) + 1) * PIS;  // rows mb+q+8
        const float* piR2 = sPi + ((mb >> 3) + 2) * PIS;  // rows mb+q+16
        const float* piR3 = sPi + ((mb >> 3) + 3) * PIS;  // rows mb+q+24
        const float* pjR  = sPj + q * PIS;

        float acc[2][8][4];
#pragma unroll
        for (int am = 0; am < 2; am++)
#pragma unroll
            for (int a = 0; a < 8; a++)
#pragma unroll
                for (int e = 0; e < 4; e++) acc[am][a][e] = 0.f;

        // ---- R5's k-loop, untouched (compiler-scheduled) ----
#pragma unroll 4
        for (int s = 0; s < 32; s++) {
            const int k1 = 8 * s + c, k2 = k1 + 4;

            float4 f0 = myB[(s * 4 + 0) * 64];
            float4 f1 = myB[(s * 4 + 1) * 64];
            float4 f2 = myB[(s * 4 + 2) * 64];
            float4 f3 = myB[(s * 4 + 3) * 64];
            uint32_t bf[8][2];
            bf[0][0] = __float_as_uint(f0.x); bf[0][1] = __float_as_uint(f0.y);
            bf[1][0] = __float_as_uint(f0.z); bf[1][1] = __float_as_uint(f0.w);
            bf[2][0] = __float_as_uint(f1.x); bf[2][1] = __float_as_uint(f1.y);
            bf[3][0] = __float_as_uint(f1.z); bf[3][1] = __float_as_uint(f1.w);
            bf[4][0] = __float_as_uint(f2.x); bf[4][1] = __float_as_uint(f2.y);
            bf[5][0] = __float_as_uint(f2.z); bf[5][1] = __float_as_uint(f2.w);
            bf[6][0] = __float_as_uint(f3.x); bf[6][1] = __float_as_uint(f3.y);
            bf[7][0] = __float_as_uint(f3.z); bf[7][1] = __float_as_uint(f3.w);

            const float pj1 = pjR[k1], pj2 = pjR[k2];

            {   // M-atom 0: rows mb+q, mb+q+8
                uint32_t af[4];
                af[0] = __float_as_uint(fmaxf(piR0[k1] + pj1, 0.f));
                af[1] = __float_as_uint(fmaxf(piR1[k1] + pj1, 0.f));
                af[2] = __float_as_uint(fmaxf(piR0[k2] + pj2, 0.f));
                af[3] = __float_as_uint(fmaxf(piR1[k2] + pj2, 0.f));
#pragma unroll
                for (int a = 0; a < 8; a++) mma_tf32(acc[0][a], af, bf[a]);
            }
            {   // M-atom 1: rows mb+q+16, mb+q+24
                uint32_t af[4];
                af[0] = __float_as_uint(fmaxf(piR2[k1] + pj1, 0.f));
                af[1] = __float_as_uint(fmaxf(piR3[k1] + pj1, 0.f));
                af[2] = __float_as_uint(fmaxf(piR2[k2] + pj2, 0.f));
                af[3] = __float_as_uint(fmaxf(piR3[k2] + pj2, 0.f));
#pragma unroll
                for (int a = 0; a < 8; a++) mma_tf32(acc[1][a], af, bf[a]);
            }
        }

        // ---- epilogue (R5) ----
#pragma unroll
        for (int am = 0; am < 2; am++) {
            float s0 = 0.f, s1 = 0.f;
#pragma unroll
            for (int a = 0; a < 8; a++) {
                int n0 = nb + 8 * a + 2 * c;
                float w0 = sW3[n0], w1 = sW3[n0 + 1];
                float bb0 = sB2[n0], bb1 = sB2[n0 + 1];
                s0 = fmaf(fmaxf(acc[am][a][0] + bb0, 0.f), w0, s0);
                s0 = fmaf(fmaxf(acc[am][a][1] + bb1, 0.f), w1, s0);
                s1 = fmaf(fmaxf(acc[am][a][2] + bb0, 0.f), w0, s1);
                s1 = fmaf(fmaxf(acc[am][a][3] + bb1, 0.f), w1, s1);
            }
            s0 += __shfl_xor_sync(0xffffffffu, s0, 1);
            s0 += __shfl_xor_sync(0xffffffffu, s0, 2);
            s1 += __shfl_xor_sync(0xffffffffu, s1, 1);
            s1 += __shfl_xor_sync(0xffffffffu, s1, 2);
            if (c == 0) {
                int m0 = mb + am * 16 + q;
                sRed[m0 * 2 + wn]       = s0;
                sRed[(m0 + 8) * 2 + wn] = s1;
            }
        }
        __syncthreads();

        if (tid < 256) {
            float s = sRed[tid * 2] + sRed[tid * 2 + 1];
            float val = tanhf(s + b3v);
            int i = i0 + (tid >> 3), j = j0 + (tid & 7);
            bool valid = (j >= i + 2) && ((j - i) != (Ndim - 1));
            outM[(b * Ndim + i) * Ndim + j] = valid ? val : 0.f;
        }
        // next-iteration staging __syncthreads guards sRed + Pi/Pj buffer reuse
    }
}

// ---------------------------------------------------------------------------
extern "C" void kernel_launch(void* const* d_in, const int* in_sizes, int n_in,
                              void* d_out, int out_size) {
    const float* x  = (const float*)d_in[0];
    const float* W1 = (const float*)d_in[1];
    const float* b1 = (const float*)d_in[2];
    const float* W2 = (const float*)d_in[3];
    const float* b2 = (const float*)d_in[4];
    const float* W3 = (const float*)d_in[5];
    const float* b3 = (const float*)d_in[6];

    float* out = (float*)d_out;
    const int matElems  = Bdim * Ndim * Ndim;
    const int tourElems = Bdim * Ndim;
    int hasTour = (out_size >= matElems + tourElems) ? 1 : 0;
    float* outTour = out;
    float* outM    = hasTour ? (out + tourElems) : out;

    // zero matrix region (covers fully-masked tiles); computed tiles overwrite
    cudaMemsetAsync(outM, 0, (size_t)matElems * sizeof(float), 0);

    dim3 g1(Bdim, Ndim / 8);
    proj_kernel<<<g1, 256>>>(x, W1, b1, outTour, hasTour);

    cudaFuncSetAttribute(pair_mma_kernel, cudaFuncAttributeMaxDynamicSharedMemorySize,
                         SMEM_BYTES);
    pair_mma_kernel<<<GRID_PAIR, NTHREADS, SMEM_BYTES>>>(W2, b2, W3, b3, outM);
}

// round 8
// speedup vs baseline: 2.1635x; 1.3759x over previous
#include <cuda_runtime.h>
#include <cuda_fp16.h>
#include <math.h>
#include <stdint.h>

#define Bdim 8
#define Ndim 256
#define Ddim 128
#define K2   256

// Scratch for per-node projections (allocation-free rule -> device globals)
__device__ float g_Pi[Bdim * Ndim * K2];
__device__ float g_Pj[Bdim * Ndim * K2];

// ---------------------------------------------------------------------------
// Kernel 1 (proven): Pi = x@W1a + x_next@W1b + b1 ; Pj = x@W1c + x_next@W1d
// ---------------------------------------------------------------------------
__global__ void __launch_bounds__(256) proj_kernel(
    const float* __restrict__ x, const float* __restrict__ W1,
    const float* __restrict__ b1, float* __restrict__ outTour, int hasTour)
{
    __shared__ float xr[9][128];
    const int b  = blockIdx.x;
    const int n0 = blockIdx.y * 8;
    const int tid = threadIdx.x;

    for (int idx = tid; idx < 9 * 128; idx += 256) {
        int r = idx >> 7, c = idx & 127;
        int n = (n0 + r) & (Ndim - 1);
        xr[r][c] = x[((b * Ndim) + n) * Ddim + c];
    }
    __syncthreads();

    const int c = tid;
    float accPi[8], accPj[8];
#pragma unroll
    for (int r = 0; r < 8; r++) { accPi[r] = 0.f; accPj[r] = 0.f; }

    for (int k = 0; k < 128; k++) {
        float wa = W1[(k      ) * 256 + c];
        float wb = W1[(k + 128) * 256 + c];
        float wc = W1[(k + 256) * 256 + c];
        float wd = W1[(k + 384) * 256 + c];
#pragma unroll
        for (int r = 0; r < 8; r++) {
            float xi = xr[r][k];
            float xn = xr[r + 1][k];
            accPi[r] = fmaf(xi, wa, accPi[r]);
            accPi[r] = fmaf(xn, wb, accPi[r]);
            accPj[r] = fmaf(xi, wc, accPj[r]);
            accPj[r] = fmaf(xn, wd, accPj[r]);
        }
    }
    const float bias = b1[c];
#pragma unroll
    for (int r = 0; r < 8; r++) {
        int n = n0 + r;
        g_Pi[((b * Ndim) + n) * K2 + c] = accPi[r] + bias;
        g_Pj[((b * Ndim) + n) * K2 + c] = accPj[r];
    }
    if (hasTour && tid < 8) outTour[b * Ndim + n0 + tid] = (float)(n0 + tid);
}

// ---------------------------------------------------------------------------
// mma.sync m16n8k16 fp16 (fp32 accum)
// ---------------------------------------------------------------------------
__device__ __forceinline__ void mma_f16(float* d, const uint32_t* a,
                                        const uint32_t* b) {
    asm volatile(
        "mma.sync.aligned.m16n8k16.row.col.f32.f16.f16.f32 "
        "{%0,%1,%2,%3},{%4,%5,%6,%7},{%8,%9},{%0,%1,%2,%3};\n"
        : "+f"(d[0]), "+f"(d[1]), "+f"(d[2]), "+f"(d[3])
        : "r"(a[0]), "r"(a[1]), "r"(a[2]), "r"(a[3]), "r"(b[0]), "r"(b[1]));
}

__device__ __forceinline__ void cpa16(uint32_t dst, const void* src) {
    asm volatile("cp.async.ca.shared.global [%0], [%1], 16;"
                 :: "r"(dst), "l"(src) : "memory");
}
__device__ __forceinline__ uint32_t smem_u32(const void* p) {
    uint32_t a;
    asm("{ .reg .u64 t; cvta.to.shared.u64 t, %1; cvt.u32.u64 %0, t; }"
        : "=r"(a) : "l"(p));
    return a;
}
// relu(p + j) for a k-pair, converted to packed half2
__device__ __forceinline__ uint32_t h2relu(float2 p, float2 j) {
    __half2 h = __floats2half2_rn(fmaxf(p.x + j.x, 0.f), fmaxf(p.y + j.y, 0.f));
    return *(uint32_t*)&h;
}
__device__ __forceinline__ uint32_t packh2(float a, float b) {
    __half2 h = __floats2half2_rn(a, b);
    return *(uint32_t*)&h;
}

// ---------------------------------------------------------------------------
// SMEM layout (floats)
// ---------------------------------------------------------------------------
#define PIS 260
#define OFF_W2F 0                         // packed fp16 B fragments: 16384 floats
#define OFF_PI0 16384                     // 32*260 = 8320
#define OFF_PI1 (OFF_PI0 + 32 * PIS)      // 24704
#define OFF_PJ0 (OFF_PI1 + 32 * PIS)      // 33024 ; 8*260 = 2080
#define OFF_PJ1 (OFF_PJ0 + 8 * PIS)       // 35104
#define OFF_B2  (OFF_PJ1 + 8 * PIS)       // 37184
#define OFF_W3  (OFF_B2 + 128)            // 37312
#define OFF_RED (OFF_W3 + 128)            // 37440 ; 512 floats
#define SMEM_FLOATS (OFF_RED + 512)       // 37952 -> 151808 bytes
#define SMEM_BYTES (SMEM_FLOATS * 4)

#define NTILES_PER_B 144                  // sum_{bi=0..7} (32 - 4*bi)
#define NTILES_TOT   (Bdim * NTILES_PER_B)    // 1152
#define GRID_PAIR    152
#define NTHREADS     512

__device__ __forceinline__ void tile_coords(int t, int& b, int& i0, int& j0) {
    b = t / NTILES_PER_B;
    int r = t - b * NTILES_PER_B;
    int bi = 0;
    while (r >= 32 - 4 * bi) { r -= 32 - 4 * bi; bi++; }
    i0 = bi * 32;
    j0 = (4 * bi + r) * 8;
}

// ---------------------------------------------------------------------------
// Kernel 2: persistent fp16 m16n8k16 pair kernel.
// CTA tile: M=256 pairs (32 i x 8 j), N=128 outs, K=256. 16 warps (8M x 2N).
// B fragments pre-converted to fp16 half2 pairs, packed conflict-free:
//   float4 idx ((s*4+g)*2+wn)*32+lane holds, for k-step s and N-atoms
//   a=2g / 2g+1:  {b0(2g), b1(2g), b0(2g+1), b1(2g+1)} as half2 in each .x/.y/.z/.w
//   where b0 = {W2[k0][n],W2[k0+1][n]}, b1 = {W2[k0+8][n],W2[k0+9][n]}, k0=16s+2c.
// cp.async double-buffered Pi/Pj tile staging (R7, proven).
// ---------------------------------------------------------------------------
__global__ void __launch_bounds__(NTHREADS, 1) pair_mma_kernel(
    const float* __restrict__ W2g, const float* __restrict__ b2g,
    const float* __restrict__ W3g, const float* __restrict__ b3g,
    float* __restrict__ outM)
{
    extern __shared__ float sm[];
    float4* sW2f4 = (float4*)(sm + OFF_W2F);
    float* sB2  = sm + OFF_B2;
    float* sW3  = sm + OFF_W3;
    float* sRed = sm + OFF_RED;
    const uint32_t sbase = smem_u32(sm);

    const int tid  = threadIdx.x;
    const int wid  = tid >> 5;
    const int lane = tid & 31;
    const int q = lane >> 2;     // fragment group id
    const int c = lane & 3;      // thread-in-group

    // --- pack fp16 B fragments (one-time, 4096 float4s) ---
    for (int idx = tid; idx < 4096; idx += NTHREADS) {
        int ln  = idx & 31;
        int wnn = (idx >> 5) & 1;
        int g   = (idx >> 6) & 3;
        int s   = idx >> 8;                 // 0..15
        int cc  = ln & 3, qq = ln >> 2;
        int k0  = 16 * s + 2 * cc;
        int n0  = 64 * wnn + 16 * g + qq;
        int n1  = n0 + 8;
        float4 v;
        uint32_t u;
        u = packh2(W2g[k0 * 128 + n0],       W2g[(k0 + 1) * 128 + n0]); v.x = __uint_as_float(u);
        u = packh2(W2g[(k0 + 8) * 128 + n0], W2g[(k0 + 9) * 128 + n0]); v.y = __uint_as_float(u);
        u = packh2(W2g[k0 * 128 + n1],       W2g[(k0 + 1) * 128 + n1]); v.z = __uint_as_float(u);
        u = packh2(W2g[(k0 + 8) * 128 + n1], W2g[(k0 + 9) * 128 + n1]); v.w = __uint_as_float(u);
        sW2f4[idx] = v;
    }
    if (tid < 128) { sB2[tid] = b2g[tid]; sW3[tid] = W3g[tid]; }
    const float b3v = b3g[0];

    const int wm = wid >> 1;
    const int wn = wid & 1;
    const int mb = wm * 32;
    const int nb = wn * 64;
    const float4* myB = sW2f4 + wn * 32 + lane;   // + (s*4+g)*64

    // --- prefetch first tile's Pi/Pj into buffer 0 ---
    {
        int b, i0, j0;
        tile_coords(blockIdx.x, b, i0, j0);
        const float* gPi = g_Pi + (size_t)(b * Ndim + i0) * K2;
        const float* gPj = g_Pj + (size_t)(b * Ndim + j0) * K2;
#pragma unroll
        for (int u = 0; u < 4; u++) {
            int idx = u * NTHREADS + tid;            // 0..2047
            int row = idx >> 6, k4 = (idx & 63) << 2;
            cpa16(sbase + (OFF_PI0 + row * PIS + k4) * 4, gPi + row * 256 + k4);
        }
        {
            int row = tid >> 6, k4 = (tid & 63) << 2;
            cpa16(sbase + (OFF_PJ0 + row * PIS + k4) * 4, gPj + row * 256 + k4);
        }
        asm volatile("cp.async.commit_group;" ::: "memory");
    }

    int cnt = 0;
    for (int t = blockIdx.x; t < NTILES_TOT; t += GRID_PAIR, cnt++) {
        const int buf = cnt & 1;

        // prefetch next tile into the other buffer, then wait for current
        if (t + GRID_PAIR < NTILES_TOT) {
            int b, i0, j0;
            tile_coords(t + GRID_PAIR, b, i0, j0);
            const float* gPi = g_Pi + (size_t)(b * Ndim + i0) * K2;
            const float* gPj = g_Pj + (size_t)(b * Ndim + j0) * K2;
            const int piO = buf ? OFF_PI0 : OFF_PI1;
            const int pjO = buf ? OFF_PJ0 : OFF_PJ1;
#pragma unroll
            for (int u = 0; u < 4; u++) {
                int idx = u * NTHREADS + tid;
                int row = idx >> 6, k4 = (idx & 63) << 2;
                cpa16(sbase + (piO + row * PIS + k4) * 4, gPi + row * 256 + k4);
            }
            {
                int row = tid >> 6, k4 = (tid & 63) << 2;
                cpa16(sbase + (pjO + row * PIS + k4) * 4, gPj + row * 256 + k4);
            }
            asm volatile("cp.async.commit_group;" ::: "memory");
            asm volatile("cp.async.wait_group 1;" ::: "memory");
        } else {
            asm volatile("cp.async.wait_group 0;" ::: "memory");
        }
        __syncthreads();   // current tile visible; also guards sRed reuse

        int b, i0, j0;
        tile_coords(t, b, i0, j0);

        const float* sPi = sm + (buf ? OFF_PI1 : OFF_PI0);
        const float* sPj = sm + (buf ? OFF_PJ1 : OFF_PJ0);
        const float* piR0 = sPi + ((mb >> 3) + 0) * PIS;  // rows mb+q
        const float* piR1 = sPi + ((mb >> 3) + 1) * PIS;  // rows mb+q+8
        const float* piR2 = sPi + ((mb >> 3) + 2) * PIS;  // rows mb+q+16
        const float* piR3 = sPi + ((mb >> 3) + 3) * PIS;  // rows mb+q+24
        const float* pjR  = sPj + q * PIS;

        float acc[2][8][4];
#pragma unroll
        for (int am = 0; am < 2; am++)
#pragma unroll
            for (int a = 0; a < 8; a++)
#pragma unroll
                for (int e = 0; e < 4; e++) acc[am][a][e] = 0.f;

        // ---- fp16 k-loop: 16 steps of k16 ----
#pragma unroll 4
        for (int s = 0; s < 16; s++) {
            const int k0 = 16 * s + 2 * c;       // k-pair 0 base
            const int k8 = k0 + 8;               // k-pair 1 base

            float4 f0 = myB[(s * 4 + 0) * 64];
            float4 f1 = myB[(s * 4 + 1) * 64];
            float4 f2 = myB[(s * 4 + 2) * 64];
            float4 f3 = myB[(s * 4 + 3) * 64];
            uint32_t bf[8][2];
            bf[0][0] = __float_as_uint(f0.x); bf[0][1] = __float_as_uint(f0.y);
            bf[1][0] = __float_as_uint(f0.z); bf[1][1] = __float_as_uint(f0.w);
            bf[2][0] = __float_as_uint(f1.x); bf[2][1] = __float_as_uint(f1.y);
            bf[3][0] = __float_as_uint(f1.z); bf[3][1] = __float_as_uint(f1.w);
            bf[4][0] = __float_as_uint(f2.x); bf[4][1] = __float_as_uint(f2.y);
            bf[5][0] = __float_as_uint(f2.z); bf[5][1] = __float_as_uint(f2.w);
            bf[6][0] = __float_as_uint(f3.x); bf[6][1] = __float_as_uint(f3.y);
            bf[7][0] = __float_as_uint(f3.z); bf[7][1] = __float_as_uint(f3.w);

            const float2 pj0 = *(const float2*)(pjR + k0);
            const float2 pj1 = *(const float2*)(pjR + k8);

            {   // M-atom 0: rows mb+q, mb+q+8
                uint32_t af[4];
                af[0] = h2relu(*(const float2*)(piR0 + k0), pj0);
                af[1] = h2relu(*(const float2*)(piR1 + k0), pj0);
                af[2] = h2relu(*(const float2*)(piR0 + k8), pj1);
                af[3] = h2relu(*(const float2*)(piR1 + k8), pj1);
#pragma unroll
                for (int a = 0; a < 8; a++) mma_f16(acc[0][a], af, bf[a]);
            }
            {   // M-atom 1: rows mb+q+16, mb+q+24
                uint32_t af[4];
                af[0] = h2relu(*(const float2*)(piR2 + k0), pj0);
                af[1] = h2relu(*(const float2*)(piR3 + k0), pj0);
                af[2] = h2relu(*(const float2*)(piR2 + k8), pj1);
                af[3] = h2relu(*(const float2*)(piR3 + k8), pj1);
#pragma unroll
                for (int a = 0; a < 8; a++) mma_f16(acc[1][a], af, bf[a]);
            }
        }

        // ---- epilogue (unchanged; D layout identical to k8 version) ----
#pragma unroll
        for (int am = 0; am < 2; am++) {
            float s0 = 0.f, s1 = 0.f;
#pragma unroll
            for (int a = 0; a < 8; a++) {
                int n0 = nb + 8 * a + 2 * c;
                float w0 = sW3[n0], w1 = sW3[n0 + 1];
                float bb0 = sB2[n0], bb1 = sB2[n0 + 1];
                s0 = fmaf(fmaxf(acc[am][a][0] + bb0, 0.f), w0, s0);
                s0 = fmaf(fmaxf(acc[am][a][1] + bb1, 0.f), w1, s0);
                s1 = fmaf(fmaxf(acc[am][a][2] + bb0, 0.f), w0, s1);
                s1 = fmaf(fmaxf(acc[am][a][3] + bb1, 0.f), w1, s1);
            }
            s0 += __shfl_xor_sync(0xffffffffu, s0, 1);
            s0 += __shfl_xor_sync(0xffffffffu, s0, 2);
            s1 += __shfl_xor_sync(0xffffffffu, s1, 1);
            s1 += __shfl_xor_sync(0xffffffffu, s1, 2);
            if (c == 0) {
                int m0 = mb + am * 16 + q;
                sRed[m0 * 2 + wn]       = s0;
                sRed[(m0 + 8) * 2 + wn] = s1;
            }
        }
        __syncthreads();

        if (tid < 256) {
            float s = sRed[tid * 2] + sRed[tid * 2 + 1];
            float val = tanhf(s + b3v);
            int i = i0 + (tid >> 3), j = j0 + (tid & 7);
            bool valid = (j >= i + 2) && ((j - i) != (Ndim - 1));
            outM[(b * Ndim + i) * Ndim + j] = valid ? val : 0.f;
        }
        // next-iteration staging __syncthreads guards sRed + Pi/Pj buffer reuse
    }
}

// ---------------------------------------------------------------------------
extern "C" void kernel_launch(void* const* d_in, const int* in_sizes, int n_in,
                              void* d_out, int out_size) {
    const float* x  = (const float*)d_in[0];
    const float* W1 = (const float*)d_in[1];
    const float* b1 = (const float*)d_in[2];
    const float* W2 = (const float*)d_in[3];
    const float* b2 = (const float*)d_in[4];
    const float* W3 = (const float*)d_in[5];
    const float* b3 = (const float*)d_in[6];

    float* out = (float*)d_out;
    const int matElems  = Bdim * Ndim * Ndim;
    const int tourElems = Bdim * Ndim;
    int hasTour = (out_size >= matElems + tourElems) ? 1 : 0;
    float* outTour = out;
    float* outM    = hasTour ? (out + tourElems) : out;

    // zero matrix region (covers fully-masked tiles); computed tiles overwrite
    cudaMemsetAsync(outM, 0, (size_t)matElems * sizeof(float), 0);

    dim3 g1(Bdim, Ndim / 8);
    proj_kernel<<<g1, 256>>>(x, W1, b1, outTour, hasTour);

    cudaFuncSetAttribute(pair_mma_kernel, cudaFuncAttributeMaxDynamicSharedMemorySize,
                         SMEM_BYTES);
    pair_mma_kernel<<<GRID_PAIR, NTHREADS, SMEM_BYTES>>>(W2, b2, W3, b3, outM);
}

// round 9
// speedup vs baseline: 2.6224x; 1.2121x over previous
#include <cuda_runtime.h>
#include <cuda_fp16.h>
#include <math.h>
#include <stdint.h>

#define Bdim 8
#define Ndim 256
#define Ddim 128
#define K2   256

// Projections now stored as fp16 (allocation-free rule -> device globals)
__device__ __half g_Pi[Bdim * Ndim * K2];   // includes b1
__device__ __half g_Pj[Bdim * Ndim * K2];

// ---------------------------------------------------------------------------
// common helpers
// ---------------------------------------------------------------------------
__device__ __forceinline__ void mma_f16(float* d, const uint32_t* a,
                                        const uint32_t* b) {
    asm volatile(
        "mma.sync.aligned.m16n8k16.row.col.f32.f16.f16.f32 "
        "{%0,%1,%2,%3},{%4,%5,%6,%7},{%8,%9},{%0,%1,%2,%3};\n"
        : "+f"(d[0]), "+f"(d[1]), "+f"(d[2]), "+f"(d[3])
        : "r"(a[0]), "r"(a[1]), "r"(a[2]), "r"(a[3]), "r"(b[0]), "r"(b[1]));
}
__device__ __forceinline__ void cpa16(uint32_t dst, const void* src) {
    asm volatile("cp.async.ca.shared.global [%0], [%1], 16;"
                 :: "r"(dst), "l"(src) : "memory");
}
__device__ __forceinline__ uint32_t smem_u32(const void* p) {
    uint32_t a;
    asm("{ .reg .u64 t; cvta.to.shared.u64 t, %1; cvt.u32.u64 %0, t; }"
        : "=r"(a) : "l"(p));
    return a;
}
__device__ __forceinline__ uint32_t packh2(float a, float b) {
    __half2 h = __floats2half2_rn(a, b);
    return *(uint32_t*)&h;
}
__device__ __forceinline__ uint32_t h2u(__half2 h) { return *(uint32_t*)&h; }

// ===========================================================================
// Kernel 1: proj as fp16 tensor GEMM.
// Pi/Pj combined: row m=(b,n): A[m] = [x(b,n,:), x(b,n+1,:)]  (K=256, fp16)
// W[k][n] (256x512): n<256 -> W1[k][n] (W1a/W1b); n>=256 -> W1[256+k][n-256].
// CTA: 64 rows x 128 cols, K=256. 256 thr = 8 warps (2 M-split x 4 N-split).
// Output: half2 stores to g_Pi (bias added) / g_Pj.
// ===========================================================================
#define PA_STR 264                       // halves per A row (528 B)
#define PW_OFF_B 0                       // packed W frags: 65536 B
#define PA_OFF_B 65536                   // A tile: 64*528 = 33792 B
#define PB1_OFF_B (PA_OFF_B + 33792)     // 99328 ; b1: 1024 B
#define SMEM_BYTES_PROJ (PB1_OFF_B + 1024)

__global__ void __launch_bounds__(256, 1) proj_mma_kernel(
    const float* __restrict__ x, const float* __restrict__ W1,
    const float* __restrict__ b1, float* __restrict__ outTour, int hasTour)
{
    extern __shared__ char smc[];
    float4* sW4 = (float4*)(smc + PW_OFF_B);
    __half* sA  = (__half*)(smc + PA_OFF_B);
    float*  sb1 = (float*)(smc + PB1_OFF_B);

    const int tid  = threadIdx.x;
    const int wid  = tid >> 5;
    const int lane = tid & 31;
    const int q = lane >> 2;
    const int c = lane & 3;
    const int nb = blockIdx.x * 128;   // N block (0,128,256,384)
    const int n0 = blockIdx.y * 64;    // row block within batch
    const int b  = blockIdx.z;

    // pack W fragments (fp16), conflict-free: float4 idx ((s*2+gg)*4+wn4)*32+lane
    for (int idx = tid; idx < 4096; idx += 256) {
        int ln  = idx & 31;
        int wn4 = (idx >> 5) & 3;
        int gg  = (idx >> 7) & 1;
        int s   = idx >> 8;
        int cc = ln & 3, qq = ln >> 2;
        int k0 = 16 * s + 2 * cc;
        int nA = nb + wn4 * 32 + (2 * gg) * 8 + qq;
        int nB = nA + 8;
        // Wv(k,n): n<256 ? W1[k*256+n] : W1[(256+k)*256 + n-256]
        const float* WA = (nA < 256) ? (W1 + nA) : (W1 + 256 * 256 + (nA - 256));
        const float* WB = (nB < 256) ? (W1 + nB) : (W1 + 256 * 256 + (nB - 256));
        float4 v;
        v.x = __uint_as_float(packh2(WA[k0 * 256],       WA[(k0 + 1) * 256]));
        v.y = __uint_as_float(packh2(WA[(k0 + 8) * 256], WA[(k0 + 9) * 256]));
        v.z = __uint_as_float(packh2(WB[k0 * 256],       WB[(k0 + 1) * 256]));
        v.w = __uint_as_float(packh2(WB[(k0 + 8) * 256], WB[(k0 + 9) * 256]));
        sW4[idx] = v;
    }
    if (tid < 256) sb1[tid] = b1[tid];

    // stage A tile: sA[m][k] = k<128 ? x[b][n0+m][k] : x[b][n0+m+1][k-128]
    for (int idx = tid; idx < 16384; idx += 256) {
        int m = idx >> 8, k = idx & 255;
        float v = (k < 128)
            ? x[((b << 8) + n0 + m) * 128 + k]
            : x[((b << 8) + ((n0 + m + 1) & 255)) * 128 + (k - 128)];
        sA[m * PA_STR + k] = __float2half(v);
    }
    __syncthreads();

    const int wm  = wid >> 2;    // 0..1 -> 32 rows
    const int wn4 = wid & 3;     // 0..3 -> 32 cols
    const float4* myW = sW4 + wn4 * 32 + lane;

    float acc[2][4][4];
#pragma unroll
    for (int am = 0; am < 2; am++)
#pragma unroll
        for (int a = 0; a < 4; a++)
#pragma unroll
            for (int e = 0; e < 4; e++) acc[am][a][e] = 0.f;

#pragma unroll 4
    for (int s = 0; s < 16; s++) {
        const int k0 = 16 * s + 2 * c;
        float4 f0 = myW[(s * 2 + 0) * 128];
        float4 f1 = myW[(s * 2 + 1) * 128];
        uint32_t bf[4][2];
        bf[0][0] = __float_as_uint(f0.x); bf[0][1] = __float_as_uint(f0.y);
        bf[1][0] = __float_as_uint(f0.z); bf[1][1] = __float_as_uint(f0.w);
        bf[2][0] = __float_as_uint(f1.x); bf[2][1] = __float_as_uint(f1.y);
        bf[3][0] = __float_as_uint(f1.z); bf[3][1] = __float_as_uint(f1.w);
#pragma unroll
        for (int am = 0; am < 2; am++) {
            const int base = wm * 32 + am * 16;
            uint32_t af[4];
            af[0] = *(const uint32_t*)(sA + (base + q) * PA_STR + k0);
            af[1] = *(const uint32_t*)(sA + (base + q + 8) * PA_STR + k0);
            af[2] = *(const uint32_t*)(sA + (base + q) * PA_STR + k0 + 8);
            af[3] = *(const uint32_t*)(sA + (base + q + 8) * PA_STR + k0 + 8);
#pragma unroll
            for (int a = 0; a < 4; a++) mma_f16(acc[am][a], af, bf[a]);
        }
    }

    // epilogue: add bias (Pi cols only), convert to half2, store
#pragma unroll
    for (int am = 0; am < 2; am++) {
#pragma unroll
        for (int a = 0; a < 4; a++) {
            int col0 = nb + wn4 * 32 + a * 8 + 2 * c;   // even
            int r0 = wm * 32 + am * 16 + q;
            float e0 = acc[am][a][0], e1 = acc[am][a][1];
            float e2 = acc[am][a][2], e3 = acc[am][a][3];
            if (col0 < 256) {
                float bb0 = sb1[col0], bb1 = sb1[col0 + 1];
                uint32_t* d0 = (uint32_t*)(g_Pi + ((b << 8) + n0 + r0) * 256 + col0);
                uint32_t* d1 = (uint32_t*)(g_Pi + ((b << 8) + n0 + r0 + 8) * 256 + col0);
                *d0 = packh2(e0 + bb0, e1 + bb1);
                *d1 = packh2(e2 + bb0, e3 + bb1);
            } else {
                int cj = col0 - 256;
                uint32_t* d0 = (uint32_t*)(g_Pj + ((b << 8) + n0 + r0) * 256 + cj);
                uint32_t* d1 = (uint32_t*)(g_Pj + ((b << 8) + n0 + r0 + 8) * 256 + cj);
                *d0 = packh2(e0, e1);
                *d1 = packh2(e2, e3);
            }
        }
    }
    if (hasTour && blockIdx.x == 0 && tid < 64)
        outTour[b * Ndim + n0 + tid] = (float)(n0 + tid);
}

// ===========================================================================
// Kernel 2: persistent fp16 m16n8k16 pair kernel (R8) with fp16 Pi/Pj and
// HADD2/HMAX2 A-build. cp.async double-buffered staging (halved bytes).
// ===========================================================================
#define PIS_H 264                           // halves per Pi/Pj row (528 B)
#define OFF_W2F_B 0                         // packed fp16 B frags: 65536 B
#define OFF_PI0_B 65536                     // 32*528 = 16896
#define OFF_PI1_B (OFF_PI0_B + 16896)       // 82432
#define OFF_PJ0_B (OFF_PI1_B + 16896)       // 99328 ; 8*528 = 4224
#define OFF_PJ1_B (OFF_PJ0_B + 4224)        // 103552
#define OFF_B2_B  (OFF_PJ1_B + 4224)        // 107776
#define OFF_W3_B  (OFF_B2_B + 512)          // 108288
#define OFF_RED_B (OFF_W3_B + 512)          // 108800 ; 512 floats
#define SMEM_BYTES_PAIR (OFF_RED_B + 2048)  // 110848

#define NTILES_PER_B 144
#define NTILES_TOT   (Bdim * NTILES_PER_B)  // 1152
#define GRID_PAIR    152
#define NTHREADS     512

__device__ __forceinline__ void tile_coords(int t, int& b, int& i0, int& j0) {
    b = t / NTILES_PER_B;
    int r = t - b * NTILES_PER_B;
    int bi = 0;
    while (r >= 32 - 4 * bi) { r -= 32 - 4 * bi; bi++; }
    i0 = bi * 32;
    j0 = (4 * bi + r) * 8;
}

__global__ void __launch_bounds__(NTHREADS, 1) pair_mma_kernel(
    const float* __restrict__ W2g, const float* __restrict__ b2g,
    const float* __restrict__ W3g, const float* __restrict__ b3g,
    float* __restrict__ outM)
{
    extern __shared__ char smc[];
    float4* sW2f4 = (float4*)(smc + OFF_W2F_B);
    float* sB2  = (float*)(smc + OFF_B2_B);
    float* sW3  = (float*)(smc + OFF_W3_B);
    float* sRed = (float*)(smc + OFF_RED_B);
    const uint32_t sbase = smem_u32(smc);

    const int tid  = threadIdx.x;
    const int wid  = tid >> 5;
    const int lane = tid & 31;
    const int q = lane >> 2;
    const int c = lane & 3;

    // pack fp16 B fragments (one-time, 4096 float4s) — R8 layout
    for (int idx = tid; idx < 4096; idx += NTHREADS) {
        int ln  = idx & 31;
        int wnn = (idx >> 5) & 1;
        int g   = (idx >> 6) & 3;
        int s   = idx >> 8;
        int cc  = ln & 3, qq = ln >> 2;
        int k0  = 16 * s + 2 * cc;
        int n0  = 64 * wnn + 16 * g + qq;
        int n1  = n0 + 8;
        float4 v;
        v.x = __uint_as_float(packh2(W2g[k0 * 128 + n0],       W2g[(k0 + 1) * 128 + n0]));
        v.y = __uint_as_float(packh2(W2g[(k0 + 8) * 128 + n0], W2g[(k0 + 9) * 128 + n0]));
        v.z = __uint_as_float(packh2(W2g[k0 * 128 + n1],       W2g[(k0 + 1) * 128 + n1]));
        v.w = __uint_as_float(packh2(W2g[(k0 + 8) * 128 + n1], W2g[(k0 + 9) * 128 + n1]));
        sW2f4[idx] = v;
    }
    if (tid < 128) { sB2[tid] = b2g[tid]; sW3[tid] = W3g[tid]; }
    const float b3v = b3g[0];

    const int wm = wid >> 1;
    const int wn = wid & 1;
    const int mb = wm * 32;
    const int nb = wn * 64;
    const float4* myB = sW2f4 + wn * 32 + lane;

    // prefetch first tile (fp16: Pi 16KB = 1024 chunks, Pj 4KB = 256 chunks)
    {
        int b, i0, j0;
        tile_coords(blockIdx.x, b, i0, j0);
        const __half* gPi = g_Pi + (size_t)(b * Ndim + i0) * K2;
        const __half* gPj = g_Pj + (size_t)(b * Ndim + j0) * K2;
#pragma unroll
        for (int u = 0; u < 2; u++) {
            int idx = u * NTHREADS + tid;
            int row = idx >> 5, ch = idx & 31;
            cpa16(sbase + OFF_PI0_B + row * 528 + ch * 16, gPi + row * 256 + ch * 8);
        }
        if (tid < 256) {
            int row = tid >> 5, ch = tid & 31;
            cpa16(sbase + OFF_PJ0_B + row * 528 + ch * 16, gPj + row * 256 + ch * 8);
        }
        asm volatile("cp.async.commit_group;" ::: "memory");
    }

    const __half2 hz = __float2half2_rn(0.f);

    int cnt = 0;
    for (int t = blockIdx.x; t < NTILES_TOT; t += GRID_PAIR, cnt++) {
        const int buf = cnt & 1;

        if (t + GRID_PAIR < NTILES_TOT) {
            int b, i0, j0;
            tile_coords(t + GRID_PAIR, b, i0, j0);
            const __half* gPi = g_Pi + (size_t)(b * Ndim + i0) * K2;
            const __half* gPj = g_Pj + (size_t)(b * Ndim + j0) * K2;
            const int piO = buf ? OFF_PI0_B : OFF_PI1_B;
            const int pjO = buf ? OFF_PJ0_B : OFF_PJ1_B;
#pragma unroll
            for (int u = 0; u < 2; u++) {
                int idx = u * NTHREADS + tid;
                int row = idx >> 5, ch = idx & 31;
                cpa16(sbase + piO + row * 528 + ch * 16, gPi + row * 256 + ch * 8);
            }
            if (tid < 256) {
                int row = tid >> 5, ch = tid & 31;
                cpa16(sbase + pjO + row * 528 + ch * 16, gPj + row * 256 + ch * 8);
            }
            asm volatile("cp.async.commit_group;" ::: "memory");
            asm volatile("cp.async.wait_group 1;" ::: "memory");
        } else {
            asm volatile("cp.async.wait_group 0;" ::: "memory");
        }
        __syncthreads();

        int b, i0, j0;
        tile_coords(t, b, i0, j0);

        const __half* sPi = (const __half*)(smc + (buf ? OFF_PI1_B : OFF_PI0_B));
        const __half* sPj = (const __half*)(smc + (buf ? OFF_PJ1_B : OFF_PJ0_B));
        const __half* piR0 = sPi + ((mb >> 3) + 0) * PIS_H;
        const __half* piR1 = sPi + ((mb >> 3) + 1) * PIS_H;
        const __half* piR2 = sPi + ((mb >> 3) + 2) * PIS_H;
        const __half* piR3 = sPi + ((mb >> 3) + 3) * PIS_H;
        const __half* pjR  = sPj + q * PIS_H;

        float acc[2][8][4];
#pragma unroll
        for (int am = 0; am < 2; am++)
#pragma unroll
            for (int a = 0; a < 8; a++)
#pragma unroll
                for (int e = 0; e < 4; e++) acc[am][a][e] = 0.f;

#pragma unroll 4
        for (int s = 0; s < 16; s++) {
            const int k0 = 16 * s + 2 * c;
            const int k8 = k0 + 8;

            float4 f0 = myB[(s * 4 + 0) * 64];
            float4 f1 = myB[(s * 4 + 1) * 64];
            float4 f2 = myB[(s * 4 + 2) * 64];
            float4 f3 = myB[(s * 4 + 3) * 64];
            uint32_t bf[8][2];
            bf[0][0] = __float_as_uint(f0.x); bf[0][1] = __float_as_uint(f0.y);
            bf[1][0] = __float_as_uint(f0.z); bf[1][1] = __float_as_uint(f0.w);
            bf[2][0] = __float_as_uint(f1.x); bf[2][1] = __float_as_uint(f1.y);
            bf[3][0] = __float_as_uint(f1.z); bf[3][1] = __float_as_uint(f1.w);
            bf[4][0] = __float_as_uint(f2.x); bf[4][1] = __float_as_uint(f2.y);
            bf[5][0] = __float_as_uint(f2.z); bf[5][1] = __float_as_uint(f2.w);
            bf[6][0] = __float_as_uint(f3.x); bf[6][1] = __float_as_uint(f3.y);
            bf[7][0] = __float_as_uint(f3.z); bf[7][1] = __float_as_uint(f3.w);

            const __half2 pj0 = *(const __half2*)(pjR + k0);
            const __half2 pj1 = *(const __half2*)(pjR + k8);

            {   // M-atom 0: rows mb+q, mb+q+8
                uint32_t af[4];
                af[0] = h2u(__hmax2(__hadd2(*(const __half2*)(piR0 + k0), pj0), hz));
                af[1] = h2u(__hmax2(__hadd2(*(const __half2*)(piR1 + k0), pj0), hz));
                af[2] = h2u(__hmax2(__hadd2(*(const __half2*)(piR0 + k8), pj1), hz));
                af[3] = h2u(__hmax2(__hadd2(*(const __half2*)(piR1 + k8), pj1), hz));
#pragma unroll
                for (int a = 0; a < 8; a++) mma_f16(acc[0][a], af, bf[a]);
            }
            {   // M-atom 1: rows mb+q+16, mb+q+24
                uint32_t af[4];
                af[0] = h2u(__hmax2(__hadd2(*(const __half2*)(piR2 + k0), pj0), hz));
                af[1] = h2u(__hmax2(__hadd2(*(const __half2*)(piR3 + k0), pj0), hz));
                af[2] = h2u(__hmax2(__hadd2(*(const __half2*)(piR2 + k8), pj1), hz));
                af[3] = h2u(__hmax2(__hadd2(*(const __half2*)(piR3 + k8), pj1), hz));
#pragma unroll
                for (int a = 0; a < 8; a++) mma_f16(acc[1][a], af, bf[a]);
            }
        }

        // epilogue (unchanged)
#pragma unroll
        for (int am = 0; am < 2; am++) {
            float s0 = 0.f, s1 = 0.f;
#pragma unroll
            for (int a = 0; a < 8; a++) {
                int n0 = nb + 8 * a + 2 * c;
                float w0 = sW3[n0], w1 = sW3[n0 + 1];
                float bb0 = sB2[n0], bb1 = sB2[n0 + 1];
                s0 = fmaf(fmaxf(acc[am][a][0] + bb0, 0.f), w0, s0);
                s0 = fmaf(fmaxf(acc[am][a][1] + bb1, 0.f), w1, s0);
                s1 = fmaf(fmaxf(acc[am][a][2] + bb0, 0.f), w0, s1);
                s1 = fmaf(fmaxf(acc[am][a][3] + bb1, 0.f), w1, s1);
            }
            s0 += __shfl_xor_sync(0xffffffffu, s0, 1);
            s0 += __shfl_xor_sync(0xffffffffu, s0, 2);
            s1 += __shfl_xor_sync(0xffffffffu, s1, 1);
            s1 += __shfl_xor_sync(0xffffffffu, s1, 2);
            if (c == 0) {
                int m0 = mb + am * 16 + q;
                sRed[m0 * 2 + wn]       = s0;
                sRed[(m0 + 8) * 2 + wn] = s1;
            }
        }
        __syncthreads();

        if (tid < 256) {
            float s = sRed[tid * 2] + sRed[tid * 2 + 1];
            float val = tanhf(s + b3v);
            int i = i0 + (tid >> 3), j = j0 + (tid & 7);
            bool valid = (j >= i + 2) && ((j - i) != (Ndim - 1));
            outM[(b * Ndim + i) * Ndim + j] = valid ? val : 0.f;
        }
        // next-iteration staging __syncthreads guards sRed + Pi/Pj buffer reuse
    }
}

// ---------------------------------------------------------------------------
extern "C" void kernel_launch(void* const* d_in, const int* in_sizes, int n_in,
                              void* d_out, int out_size) {
    const float* x  = (const float*)d_in[0];
    const float* W1 = (const float*)d_in[1];
    const float* b1 = (const float*)d_in[2];
    const float* W2 = (const float*)d_in[3];
    const float* b2 = (const float*)d_in[4];
    const float* W3 = (const float*)d_in[5];
    const float* b3 = (const float*)d_in[6];

    float* out = (float*)d_out;
    const int matElems  = Bdim * Ndim * Ndim;
    const int tourElems = Bdim * Ndim;
    int hasTour = (out_size >= matElems + tourElems) ? 1 : 0;
    float* outTour = out;
    float* outM    = hasTour ? (out + tourElems) : out;

    cudaMemsetAsync(outM, 0, (size_t)matElems * sizeof(float), 0);

    cudaFuncSetAttribute(proj_mma_kernel, cudaFuncAttributeMaxDynamicSharedMemorySize,
                         SMEM_BYTES_PROJ);
    dim3 g1(4, 4, Bdim);   // Nblocks x rowblocks x batch = 128 CTAs
    proj_mma_kernel<<<g1, 256, SMEM_BYTES_PROJ>>>(x, W1, b1, outTour, hasTour);

    cudaFuncSetAttribute(pair_mma_kernel, cudaFuncAttributeMaxDynamicSharedMemorySize,
                         SMEM_BYTES_PAIR);
    pair_mma_kernel<<<GRID_PAIR, NTHREADS, SMEM_BYTES_PAIR>>>(W2, b2, W3, b3, outM);
}